// round 3
// baseline (speedup 1.0000x reference)
#include <cuda_runtime.h>
#include <cuda_bf16.h>

// ---------------------------------------------------------------------------
// TiaRaGNN: time-aware random-walk diffusion + 2x GCN + linear readout
// CSR-gather SpMM design (no float atomics in the aggregation).
//
// edge_index may arrive as int64 (reference dtype) or int32 (harness
// downcast). A detection kernel probes the layout; all edge accesses branch
// on the uniform flag and clamp into [0,N) so no input can fault the GPU.
// ---------------------------------------------------------------------------

#define NN   100000
#define EE   1600000
#define HH   64
#define FIN  128
#define TT   10
#define ALPHA 0.1f

#define SCAN_ELEMS 1024
#define NBLK ((NN + SCAN_ELEMS - 1) / SCAN_ELEMS)   // 98

// ------------------------- device scratch (static) -------------------------
__device__ float    g_edge [EE];       // decay -> ew (in place)
__device__ float    g_nodeA[NN];       // deg   -> dinv   (in place)
__device__ float    g_nodeB[NN];       // deg2  -> dinv2  (in place)
__device__ int      g_cnt  [NN];       // in-degree histogram (by dst)
__device__ int      g_rowptr[NN + 1];  // CSR row pointers (by dst)
__device__ int      g_pos  [NN];       // fill cursors
__device__ int      g_bsum [NBLK];     // scan block sums
__device__ int      g_esrc [EE];       // CSR: src node per edge
__device__ float    g_enorm[EE];       // CSR: norm weight per edge
__device__ float    g_h    [NN * HH];  // GEMM output of current layer
__device__ float    g_hout [NN * HH];  // layer output after ReLU
__device__ unsigned g_tmax_bits;
__device__ int      g_is64;            // 1 if edge_index is int64

// --------------------------- edge index access ------------------------------
__device__ __forceinline__ int clampN(int v) {
    return min(max(v, 0), NN - 1);
}
__device__ __forceinline__ int e_src(const void* ei, int is64, int e) {
    int v = is64 ? (int)((const long long*)ei)[e] : ((const int*)ei)[e];
    return clampN(v);
}
__device__ __forceinline__ int e_dst(const void* ei, int is64, int e) {
    int v = is64 ? (int)((const long long*)ei)[EE + e] : ((const int*)ei)[EE + e];
    return clampN(v);
}

// ---------------------------- dtype detection -------------------------------
__global__ void k_detect(const void* ei) {
    if (threadIdx.x == 0 && blockIdx.x == 0) {
        const long long* p = (const long long*)ei;
        int ok = 1;
        for (int i = 0; i < 64; i++) {
            long long v = p[i];
            if (v < 0 || v >= NN) ok = 0;     // int32 pairs read as i64 are huge
        }
        g_is64 = ok;
    }
}

// ------------------------------ init ---------------------------------------
__global__ void k_init_nodes() {
    int i = blockIdx.x * blockDim.x + threadIdx.x;
    if (i < NN) { g_nodeA[i] = 0.f; g_nodeB[i] = 0.f; g_cnt[i] = 0; }
    if (i == 0) g_tmax_bits = 0u;   // edge_time in [0,1)
}

// ------------------------------- tmax reduce --------------------------------
__global__ void k_tmax(const float* __restrict__ et) {
    unsigned m = 0u;
    for (int i = blockIdx.x * blockDim.x + threadIdx.x; i < EE;
         i += gridDim.x * blockDim.x)
        m = max(m, __float_as_uint(et[i]));   // valid: et >= 0
    #pragma unroll
    for (int o = 16; o; o >>= 1)
        m = max(m, __shfl_xor_sync(0xFFFFFFFFu, m, o));
    if ((threadIdx.x & 31) == 0) atomicMax(&g_tmax_bits, m);
}

// ----------------------- edge pipeline (decay / norm) -----------------------
__global__ void k_decay_deg(const void* __restrict__ ei,
                            const float* __restrict__ et) {
    int e = blockIdx.x * blockDim.x + threadIdx.x;
    if (e >= EE) return;
    int is64 = g_is64;
    float tmax = __uint_as_float(g_tmax_bits);
    float d = __expf(ALPHA * (et[e] - tmax));      // exp(-a*(tmax - t))
    g_edge[e] = d;
    atomicAdd(&g_nodeA[e_src(ei, is64, e)], d);    // deg over row
}

__global__ void k_dinv() {
    int i = blockIdx.x * blockDim.x + threadIdx.x;
    if (i >= NN) return;
    float d = g_nodeA[i];
    g_nodeA[i] = (d > 0.f) ? rsqrtf(d) : 0.f;
}

__global__ void k_ew_deg2_cnt(const void* __restrict__ ei) {
    int e = blockIdx.x * blockDim.x + threadIdx.x;
    if (e >= EE) return;
    int is64 = g_is64;
    int r = e_src(ei, is64, e);
    int c = e_dst(ei, is64, e);
    float w = g_nodeA[r] * g_edge[e] * g_nodeA[c];
    g_edge[e] = w;
    atomicAdd(&g_nodeB[c], w);                     // deg2 over dst
    atomicAdd(&g_cnt[c], 1);                       // in-degree histogram
}

__global__ void k_dinv2() {
    int i = blockIdx.x * blockDim.x + threadIdx.x;
    if (i >= NN) return;
    g_nodeB[i] = rsqrtf(g_nodeB[i] + 1.0f);        // self loop adds 1; > 0
}

// --------------------- exclusive scan of g_cnt -> g_rowptr ------------------
__global__ __launch_bounds__(256) void k_scan_local() {
    __shared__ int wsum[8];
    int base = blockIdx.x * SCAN_ELEMS;
    int t = threadIdx.x, lane = t & 31, wid = t >> 5;

    int v[4], s = 0;
    #pragma unroll
    for (int i = 0; i < 4; i++) {
        int idx = base + t * 4 + i;
        v[i] = (idx < NN) ? g_cnt[idx] : 0;
        s += v[i];
    }
    int x = s;
    #pragma unroll
    for (int o = 1; o < 32; o <<= 1) {
        int y = __shfl_up_sync(0xFFFFFFFFu, x, o);
        if (lane >= o) x += y;
    }
    if (lane == 31) wsum[wid] = x;
    __syncthreads();
    if (wid == 0) {
        int w = (lane < 8) ? wsum[lane] : 0;
        #pragma unroll
        for (int o = 1; o < 8; o <<= 1) {
            int y = __shfl_up_sync(0xFFFFFFFFu, w, o);
            if (lane >= o) w += y;
        }
        if (lane < 8) wsum[lane] = w;   // inclusive warp-sum scan
    }
    __syncthreads();
    int excl = x - s + ((wid > 0) ? wsum[wid - 1] : 0);
    int run = excl;
    #pragma unroll
    for (int i = 0; i < 4; i++) {
        int idx = base + t * 4 + i;
        if (idx < NN) g_rowptr[idx] = run;
        run += v[i];
    }
    if (t == 0) g_bsum[blockIdx.x] = wsum[7];       // block total
}

__global__ __launch_bounds__(128) void k_scan_mid() {
    __shared__ int ws[4];
    int t = threadIdx.x, lane = t & 31, wid = t >> 5;
    int v = (t < NBLK) ? g_bsum[t] : 0;
    int x = v;
    #pragma unroll
    for (int o = 1; o < 32; o <<= 1) {
        int y = __shfl_up_sync(0xFFFFFFFFu, x, o);
        if (lane >= o) x += y;
    }
    if (lane == 31) ws[wid] = x;
    __syncthreads();
    if (t == 0) {
        int s = 0;
        #pragma unroll
        for (int i = 0; i < 4; i++) { int tmp = ws[i]; ws[i] = s; s += tmp; }
    }
    __syncthreads();
    int excl = x - v + ws[wid];
    if (t < NBLK) g_bsum[t] = excl;
}

__global__ void k_scan_add() {
    int i = blockIdx.x * blockDim.x + threadIdx.x;
    if (i >= NN) return;
    int rp = g_rowptr[i] + g_bsum[i / SCAN_ELEMS];
    g_rowptr[i] = rp;
    g_pos[i] = rp;
    if (i == 0) g_rowptr[NN] = EE;
}

// ------------------ final norm + CSR fill (counting sort) -------------------
__global__ void k_norm_fill(const void* __restrict__ ei) {
    int e = blockIdx.x * blockDim.x + threadIdx.x;
    if (e >= EE) return;
    int is64 = g_is64;
    int r = e_src(ei, is64, e);
    int c = e_dst(ei, is64, e);
    float nm = g_edge[e] * g_nodeB[r] * g_nodeB[c];
    int p = atomicAdd(&g_pos[c], 1);
    p = min(max(p, 0), EE - 1);               // defensive
    g_esrc[p]  = r;
    g_enorm[p] = nm;
}

// --------------------------------- GEMM -------------------------------------
// g_h[N,64] = X[N,K] @ W[K,64].  32 rows/block, 256 threads.
template <int K, bool FROM_HOUT>
__global__ __launch_bounds__(256) void k_gemm(const float* __restrict__ Xext,
                                              const float* __restrict__ W) {
    __shared__ float Xs[32 * K];
    const float* X = FROM_HOUT ? (const float*)g_hout : Xext;
    int row0 = blockIdx.x * 32;

    for (int i = threadIdx.x; i < 32 * K; i += 256) {
        int r = i / K, k = i - r * K;
        int gr = row0 + r;
        Xs[i] = (gr < NN) ? X[(long)gr * K + k] : 0.f;
    }
    __syncthreads();

    int tx = threadIdx.x & 63;   // output column
    int ty = threadIdx.x >> 6;   // 0..3, row phase
    float acc[8];
    #pragma unroll
    for (int i = 0; i < 8; i++) acc[i] = 0.f;

    #pragma unroll 4
    for (int k = 0; k < K; k++) {
        float w = W[k * 64 + tx];                // coalesced, L1-cached
        #pragma unroll
        for (int i = 0; i < 8; i++)
            acc[i] += Xs[(ty + 4 * i) * K + k] * w;   // smem broadcast
    }

    #pragma unroll
    for (int i = 0; i < 8; i++) {
        int r = row0 + ty + 4 * i;
        if (r < NN) g_h[r * 64 + tx] = acc[i];
    }
}

// -------------------- SpMM gather + self loop + bias + ReLU -----------------
// One warp per destination node. Edge (src,norm) pairs loaded coalesced by
// lanes and broadcast via shfl; h[src] rows gathered 128B-coalesced from L2.
__global__ __launch_bounds__(256) void k_spmm(const float* __restrict__ b) {
    int n = blockIdx.x * 8 + (threadIdx.x >> 5);
    if (n >= NN) return;
    int lane = threadIdx.x & 31;

    int beg = g_rowptr[n], end = g_rowptr[n + 1];
    float a0 = 0.f, a1 = 0.f;

    for (int base = beg; base < end; base += 32) {
        int m = min(32, end - base);
        int   sv = 0; float nv = 0.f;
        if (lane < m) { sv = g_esrc[base + lane]; nv = g_enorm[base + lane]; }
        for (int k = 0; k < m; k++) {
            int   s  = __shfl_sync(0xFFFFFFFFu, sv, k);
            float nm = __shfl_sync(0xFFFFFFFFu, nv, k);
            a0 += nm * g_h[s * 64 + lane];
            a1 += nm * g_h[s * 64 + 32 + lane];
        }
    }

    float dv = g_nodeB[n];            // dinv2
    float sl = dv * dv;               // self-loop weight (w=1 both ends)
    a0 += sl * g_h[n * 64 + lane]      + b[lane];
    a1 += sl * g_h[n * 64 + 32 + lane] + b[32 + lane];
    g_hout[n * 64 + lane]      = fmaxf(a0, 0.f);
    g_hout[n * 64 + 32 + lane] = fmaxf(a1, 0.f);
}

// -------------------------------- readout -----------------------------------
__global__ __launch_bounds__(256) void k_readout(const float* __restrict__ Wout,
                                                 const float* __restrict__ bout,
                                                 float* __restrict__ out) {
    __shared__ float Ws[HH * TT + TT];
    for (int i = threadIdx.x; i < HH * TT + TT; i += 256)
        Ws[i] = (i < HH * TT) ? Wout[i] : bout[i - HH * TT];
    __syncthreads();

    int n = blockIdx.x * blockDim.x + threadIdx.x;
    if (n >= NN) return;

    float acc[TT];
    #pragma unroll
    for (int j = 0; j < TT; j++) acc[j] = Ws[HH * TT + j];

    const float4* hr = (const float4*)&g_hout[n * HH];
    #pragma unroll
    for (int q = 0; q < HH / 4; q++) {
        float4 h = hr[q];
        #pragma unroll
        for (int j = 0; j < TT; j++) {
            acc[j] += h.x * Ws[(4 * q + 0) * TT + j];
            acc[j] += h.y * Ws[(4 * q + 1) * TT + j];
            acc[j] += h.z * Ws[(4 * q + 2) * TT + j];
            acc[j] += h.w * Ws[(4 * q + 3) * TT + j];
        }
    }
    #pragma unroll
    for (int j = 0; j < TT; j++) out[n * TT + j] = acc[j];
}

// --------------------------------- launch -----------------------------------
extern "C" void kernel_launch(void* const* d_in, const int* in_sizes, int n_in,
                              void* d_out, int out_size) {
    const float* x    = (const float*)d_in[0];
    const void*  ei   = d_in[1];
    const float* et   = (const float*)d_in[2];
    const float* W1   = (const float*)d_in[3];
    const float* b1   = (const float*)d_in[4];
    const float* W2   = (const float*)d_in[5];
    const float* b2   = (const float*)d_in[6];
    const float* Wout = (const float*)d_in[7];
    const float* bout = (const float*)d_in[8];
    float*       out  = (float*)d_out;

    const int NB = (NN + 255) / 256;       // 391
    const int EB = (EE + 255) / 256;       // 6250
    const int GB = (NN + 31) / 32;         // 3125 (gemm blocks)
    const int PB = (NN + 7) / 8;           // 12500 (spmm blocks)

    // ---- dtype probe + edge preprocessing + CSR build ----
    k_detect<<<1, 32>>>(ei);
    k_init_nodes<<<NB, 256>>>();
    k_tmax<<<512, 256>>>(et);
    k_decay_deg<<<EB, 256>>>(ei, et);
    k_dinv<<<NB, 256>>>();
    k_ew_deg2_cnt<<<EB, 256>>>(ei);
    k_dinv2<<<NB, 256>>>();
    k_scan_local<<<NBLK, 256>>>();
    k_scan_mid<<<1, 128>>>();
    k_scan_add<<<NB, 256>>>();
    k_norm_fill<<<EB, 256>>>(ei);

    // ---- layer 1 ----
    k_gemm<FIN, false><<<GB, 256>>>(x, W1);
    k_spmm<<<PB, 256>>>(b1);

    // ---- layer 2 ----
    k_gemm<HH, true><<<GB, 256>>>(x, W2);
    k_spmm<<<PB, 256>>>(b2);

    // ---- readout ----
    k_readout<<<NB, 256>>>(Wout, bout, out);
}

// round 6
// speedup vs baseline: 1.0177x; 1.0177x over previous
#include <cuda_runtime.h>
#include <cuda_bf16.h>

// ---------------------------------------------------------------------------
// TiaRaGNN: time-aware random-walk diffusion + 2x GCN + linear readout
// CSR-gather SpMM, fused readout epilogue. No inline PTX (R4/R5 f32x2 asm
// correlated with container death; reverted, structure kept).
// ---------------------------------------------------------------------------

#define NN   100000
#define EE   1600000
#define HH   64
#define FIN  128
#define TT   10
#define ALPHA 0.1f

#define SCAN_ELEMS 1024
#define NBLK ((NN + SCAN_ELEMS - 1) / SCAN_ELEMS)   // 98

// ------------------------- device scratch (static) -------------------------
__device__ float    g_edge [EE];       // decay -> ew (in place)
__device__ int      g_src  [EE];       // int32 src
__device__ int      g_dst  [EE];       // int32 dst
__device__ float    g_nodeA[NN];       // deg   -> dinv   (in place)
__device__ float    g_nodeB[NN];       // deg2  -> dinv2  (in place)
__device__ int      g_cnt  [NN];       // in-degree histogram (by dst)
__device__ int      g_rowptr[NN + 1];  // CSR row pointers (by dst)
__device__ int      g_pos  [NN];       // fill cursors
__device__ int      g_bsum [NBLK];     // scan block sums
__device__ int2     g_epack[EE];       // CSR: {src, float_bits(norm)}
__device__ float    g_h    [NN * HH];  // GEMM output of current layer
__device__ float    g_hout [NN * HH];  // layer output after ReLU
__device__ unsigned g_tmax_bits;
__device__ int      g_is64;            // 1 if edge_index is int64

// ------------------------------ helpers ------------------------------------
__device__ __forceinline__ int clampN(int v) { return min(max(v, 0), NN - 1); }

// --------------------------- init + dtype probe -----------------------------
__global__ void k_init(const void* ei) {
    int i = blockIdx.x * blockDim.x + threadIdx.x;
    if (i < NN) { g_nodeA[i] = 0.f; g_nodeB[i] = 0.f; g_cnt[i] = 0; }
    if (i == 0) {
        g_tmax_bits = 0u;                 // edge_time >= 0
        const long long* p = (const long long*)ei;
        int ok = 1;
        for (int j = 0; j < 64; j++) {
            long long v = p[j];
            if (v < 0 || v >= NN) ok = 0; // int32 pairs read as i64 are huge
        }
        g_is64 = ok;
    }
}

// ------------------------------- tmax reduce --------------------------------
__global__ void k_tmax(const float* __restrict__ et) {
    unsigned m = 0u;
    for (int i = blockIdx.x * blockDim.x + threadIdx.x; i < EE;
         i += gridDim.x * blockDim.x)
        m = max(m, __float_as_uint(et[i]));
    #pragma unroll
    for (int o = 16; o; o >>= 1)
        m = max(m, __shfl_xor_sync(0xFFFFFFFFu, m, o));
    if ((threadIdx.x & 31) == 0) atomicMax(&g_tmax_bits, m);
}

// ---- pass 1: decode indices -> int32, decay, deg(by src), cnt(by dst) ------
__global__ void k_prep1(const void* __restrict__ ei,
                        const float* __restrict__ et) {
    int e = blockIdx.x * blockDim.x + threadIdx.x;
    if (e >= EE) return;
    int is64 = g_is64;
    int r, c;
    if (is64) {
        r = (int)((const long long*)ei)[e];
        c = (int)((const long long*)ei)[EE + e];
    } else {
        r = ((const int*)ei)[e];
        c = ((const int*)ei)[EE + e];
    }
    r = clampN(r); c = clampN(c);
    g_src[e] = r; g_dst[e] = c;
    float tmax = __uint_as_float(g_tmax_bits);
    float d = __expf(ALPHA * (et[e] - tmax));
    g_edge[e] = d;
    atomicAdd(&g_nodeA[r], d);
    atomicAdd(&g_cnt[c], 1);
}

__global__ void k_dinv() {
    int i = blockIdx.x * blockDim.x + threadIdx.x;
    if (i >= NN) return;
    float d = g_nodeA[i];
    g_nodeA[i] = (d > 0.f) ? rsqrtf(d) : 0.f;
}

// ---- pass 2: symmetric-normalized weight, deg2(by dst) ---------------------
__global__ void k_prep2() {
    int e = blockIdx.x * blockDim.x + threadIdx.x;
    if (e >= EE) return;
    int r = g_src[e], c = g_dst[e];
    float w = g_nodeA[r] * g_edge[e] * g_nodeA[c];
    g_edge[e] = w;
    atomicAdd(&g_nodeB[c], w);
}

// --------------------- exclusive scan of g_cnt -> g_rowptr ------------------
__global__ __launch_bounds__(256) void k_scan_local() {
    __shared__ int wsum[8];
    int base = blockIdx.x * SCAN_ELEMS;
    int t = threadIdx.x, lane = t & 31, wid = t >> 5;

    int v[4], s = 0;
    #pragma unroll
    for (int i = 0; i < 4; i++) {
        int idx = base + t * 4 + i;
        v[i] = (idx < NN) ? g_cnt[idx] : 0;
        s += v[i];
    }
    int x = s;
    #pragma unroll
    for (int o = 1; o < 32; o <<= 1) {
        int y = __shfl_up_sync(0xFFFFFFFFu, x, o);
        if (lane >= o) x += y;
    }
    if (lane == 31) wsum[wid] = x;
    __syncthreads();
    if (wid == 0) {
        int w = (lane < 8) ? wsum[lane] : 0;
        #pragma unroll
        for (int o = 1; o < 8; o <<= 1) {
            int y = __shfl_up_sync(0xFFFFFFFFu, w, o);
            if (lane >= o) w += y;
        }
        if (lane < 8) wsum[lane] = w;
    }
    __syncthreads();
    int excl = x - s + ((wid > 0) ? wsum[wid - 1] : 0);
    int run = excl;
    #pragma unroll
    for (int i = 0; i < 4; i++) {
        int idx = base + t * 4 + i;
        if (idx < NN) g_rowptr[idx] = run;
        run += v[i];
    }
    if (t == 0) g_bsum[blockIdx.x] = wsum[7];
}

__global__ __launch_bounds__(128) void k_scan_mid() {
    __shared__ int ws[4];
    int t = threadIdx.x, lane = t & 31, wid = t >> 5;
    int v = (t < NBLK) ? g_bsum[t] : 0;
    int x = v;
    #pragma unroll
    for (int o = 1; o < 32; o <<= 1) {
        int y = __shfl_up_sync(0xFFFFFFFFu, x, o);
        if (lane >= o) x += y;
    }
    if (lane == 31) ws[wid] = x;
    __syncthreads();
    if (t == 0) {
        int s = 0;
        #pragma unroll
        for (int i = 0; i < 4; i++) { int tmp = ws[i]; ws[i] = s; s += tmp; }
    }
    __syncthreads();
    int excl = x - v + ws[wid];
    if (t < NBLK) g_bsum[t] = excl;
}

// ---- pass 3 of scan, fused with dinv2 --------------------------------------
__global__ void k_scan_add_dinv2() {
    int i = blockIdx.x * blockDim.x + threadIdx.x;
    if (i >= NN) return;
    int rp = g_rowptr[i] + g_bsum[i / SCAN_ELEMS];
    g_rowptr[i] = rp;
    g_pos[i] = rp;
    g_nodeB[i] = rsqrtf(g_nodeB[i] + 1.0f);        // self loop adds 1; > 0
    if (i == 0) g_rowptr[NN] = EE;
}

// ------------------ final norm + CSR fill (counting sort) -------------------
__global__ void k_fill() {
    int e = blockIdx.x * blockDim.x + threadIdx.x;
    if (e >= EE) return;
    int r = g_src[e], c = g_dst[e];
    float nm = g_edge[e] * g_nodeB[r] * g_nodeB[c];
    int p = atomicAdd(&g_pos[c], 1);
    p = min(max(p, 0), EE - 1);               // defensive
    g_epack[p] = make_int2(r, __float_as_int(nm));
}

// --------------------------------- GEMM -------------------------------------
// g_h[N,64] = X[N,K] @ W[K,64].  32 rows/block, 256 threads (R3-proven).
template <int K, bool FROM_HOUT>
__global__ __launch_bounds__(256) void k_gemm(const float* __restrict__ Xext,
                                              const float* __restrict__ W) {
    __shared__ float Xs[32 * K];
    const float* X = FROM_HOUT ? (const float*)g_hout : Xext;
    int row0 = blockIdx.x * 32;

    const float4* X4 = (const float4*)X;
    for (int i = threadIdx.x; i < 32 * (K / 4); i += 256) {
        int r = i / (K / 4), q = i - r * (K / 4);
        int gr = row0 + r;
        float4 v = (gr < NN) ? X4[(long)gr * (K / 4) + q]
                             : make_float4(0.f, 0.f, 0.f, 0.f);
        ((float4*)Xs)[i] = v;
    }
    __syncthreads();

    int tx = threadIdx.x & 63;   // output column
    int ty = threadIdx.x >> 6;   // 0..3, row phase
    float acc[8];
    #pragma unroll
    for (int i = 0; i < 8; i++) acc[i] = 0.f;

    #pragma unroll 4
    for (int k = 0; k < K; k++) {
        float w = W[k * 64 + tx];                // coalesced, L1-cached
        #pragma unroll
        for (int i = 0; i < 8; i++)
            acc[i] += Xs[(ty + 4 * i) * K + k] * w;   // smem broadcast
    }

    #pragma unroll
    for (int i = 0; i < 8; i++) {
        int r = row0 + ty + 4 * i;
        if (r < NN) g_h[r * 64 + tx] = acc[i];
    }
}

// -------------- SpMM gather + self loop + bias + ReLU (+readout) ------------
// One warp per destination node; lane holds feature pair (2*lane, 2*lane+1).
// Edges packed as int2{src, norm_bits}: one broadcast LDG.64 per edge; h rows
// gathered as float2 (one LDG.64 per lane covers 256B/row). Unroll-4 keeps
// ~4 gathers in flight per warp.
template <bool READOUT>
__global__ __launch_bounds__(256) void k_spmm(const float* __restrict__ b,
                                              const float* __restrict__ Wro,
                                              const float* __restrict__ bro,
                                              float* __restrict__ out) {
    __shared__ float Wt[TT * HH + TT];   // transposed Wout + bout
    if (READOUT) {
        for (int i = threadIdx.x; i < TT * HH; i += 256) {
            int j = i >> 6, f = i & 63;
            Wt[i] = Wro[f * TT + j];
        }
        if (threadIdx.x < TT) Wt[TT * HH + threadIdx.x] = bro[threadIdx.x];
        __syncthreads();
    }

    int n = blockIdx.x * 8 + (threadIdx.x >> 5);   // 12500*8 == NN exactly
    int lane = threadIdx.x & 31;
    int beg = g_rowptr[n], end = g_rowptr[n + 1];

    const float2* h2 = (const float2*)g_h;
    float ax0 = 0.f, ay0 = 0.f, ax1 = 0.f, ay1 = 0.f;

    int k = beg;
    for (; k + 4 <= end; k += 4) {
        int2 p0 = g_epack[k];
        int2 p1 = g_epack[k + 1];
        int2 p2 = g_epack[k + 2];
        int2 p3 = g_epack[k + 3];
        float2 v0 = h2[p0.x * 32 + lane];
        float2 v1 = h2[p1.x * 32 + lane];
        float2 v2 = h2[p2.x * 32 + lane];
        float2 v3 = h2[p3.x * 32 + lane];
        float n0 = __int_as_float(p0.y);
        float n1 = __int_as_float(p1.y);
        float n2 = __int_as_float(p2.y);
        float n3 = __int_as_float(p3.y);
        ax0 += n0 * v0.x; ay0 += n0 * v0.y;
        ax1 += n1 * v1.x; ay1 += n1 * v1.y;
        ax0 += n2 * v2.x; ay0 += n2 * v2.y;
        ax1 += n3 * v3.x; ay1 += n3 * v3.y;
    }
    for (; k < end; k++) {
        int2 pk = g_epack[k];
        float2 v = h2[pk.x * 32 + lane];
        float nm = __int_as_float(pk.y);
        ax0 += nm * v.x; ay0 += nm * v.y;
    }
    float ax = ax0 + ax1, ay = ay0 + ay1;

    float dv = g_nodeB[n];
    float sl = dv * dv;                          // self-loop weight
    float2 hv = h2[n * 32 + lane];
    float2 bv = ((const float2*)b)[lane];
    float r0 = fmaxf(ax + sl * hv.x + bv.x, 0.f);
    float r1 = fmaxf(ay + sl * hv.y + bv.y, 0.f);

    if (!READOUT) {
        ((float2*)g_hout)[n * 32 + lane] = make_float2(r0, r1);
    } else {
        float p[TT];
        #pragma unroll
        for (int j = 0; j < TT; j++) {
            float2 w = ((const float2*)(Wt + j * HH))[lane];
            p[j] = r0 * w.x + r1 * w.y;
        }
        #pragma unroll
        for (int o = 16; o; o >>= 1) {
            #pragma unroll
            for (int j = 0; j < TT; j++)
                p[j] += __shfl_xor_sync(0xFFFFFFFFu, p[j], o);
        }
        #pragma unroll
        for (int j = 0; j < TT; j++)
            if (lane == j) out[n * TT + j] = p[j] + Wt[TT * HH + j];
    }
}

// --------------------------------- launch -----------------------------------
extern "C" void kernel_launch(void* const* d_in, const int* in_sizes, int n_in,
                              void* d_out, int out_size) {
    const float* x    = (const float*)d_in[0];
    const void*  ei   = d_in[1];
    const float* et   = (const float*)d_in[2];
    const float* W1   = (const float*)d_in[3];
    const float* b1   = (const float*)d_in[4];
    const float* W2   = (const float*)d_in[5];
    const float* b2   = (const float*)d_in[6];
    const float* Wout = (const float*)d_in[7];
    const float* bout = (const float*)d_in[8];
    float*       out  = (float*)d_out;

    const int NB = (NN + 255) / 256;       // 391
    const int EB = (EE + 255) / 256;       // 6250
    const int GB = (NN + 31) / 32;         // 3125 (gemm blocks)
    const int PB = NN / 8;                 // 12500 (spmm blocks, exact)

    // ---- preprocessing + CSR build ----
    k_init<<<NB, 256>>>(ei);
    k_tmax<<<512, 256>>>(et);
    k_prep1<<<EB, 256>>>(ei, et);
    k_dinv<<<NB, 256>>>();
    k_prep2<<<EB, 256>>>();
    k_scan_local<<<NBLK, 256>>>();
    k_scan_mid<<<1, 128>>>();
    k_scan_add_dinv2<<<NB, 256>>>();
    k_fill<<<EB, 256>>>();

    // ---- layer 1 ----
    k_gemm<FIN, false><<<GB, 256>>>(x, W1);
    k_spmm<false><<<PB, 256>>>(b1, nullptr, nullptr, nullptr);

    // ---- layer 2 + fused readout ----
    k_gemm<HH, true><<<GB, 256>>>(x, W2);
    k_spmm<true><<<PB, 256>>>(b2, Wout, bout, out);
}